// round 16
// baseline (speedup 1.0000x reference)
#include <cuda_runtime.h>
#include <cuda_fp16.h>
#include <cstdint>

#define NN    20000
#define DD    32
#define HH    64
#define G4    256   // 4*H
#define MT    32    // nodes per tile
#define NTILE (NN / MT)        // 625 tiles
#define NCTA  ((NTILE + 1)/2)  // 313 CTAs, 2 tiles each
#define XSTG  17056            // one P-stage buffer

// ---------------- scratch ----------------
__device__ int    g_nbr_sorted[NN * DD];
__device__ __half g_P16a[(size_t)NN * G4];   // double-buffered fp16 projections
__device__ __half g_P16b[(size_t)NN * G4];
__device__ __half g_hf16[(size_t)NN * HH];   // fp16 layer outputs (combine-x)

// ---------------- helpers ----------------
__device__ __forceinline__ uint32_t pack2(float a, float b) {
    __half2 h = __floats2half2_rn(a, b);
    return *reinterpret_cast<uint32_t*>(&h);
}
__device__ __forceinline__ uint32_t pack2f(float2 v) {
    __half2 h = __floats2half2_rn(v.x, v.y);
    return *reinterpret_cast<uint32_t*>(&h);
}
__device__ __forceinline__ __half2 tanh_h2(__half2 x) {
    uint32_t xi = *reinterpret_cast<uint32_t*>(&x);
    uint32_t yi;
    asm("tanh.approx.f16x2 %0, %1;" : "=r"(yi) : "r"(xi));
    return *reinterpret_cast<__half2*>(&yi);
}
__device__ __forceinline__ __half2 sig_h2(__half2 x) {
    const __half2 h = __float2half2_rn(0.5f);
    return __hfma2(tanh_h2(__hmul2(x, h)), h, h);
}
__device__ __forceinline__ void cp_async16(uint32_t dst_smem, const void* src) {
    asm volatile("cp.async.ca.shared.global [%0], [%1], 16;" :: "r"(dst_smem), "l"(src));
}

// ---------------- layer-0 proj: P16a = x3 @ W_ih^T + b ----------------
__global__ __launch_bounds__(256) void proj16_l0_kernel(const float* __restrict__ src,
                                                        const float* __restrict__ W_ih,
                                                        const float* __restrict__ b_ih,
                                                        const float* __restrict__ b_hh) {
    __shared__ float hrow[16 * 3];
    const int j    = threadIdx.x;
    const int base = blockIdx.x * 16;

    float w0 = __ldg(&W_ih[j * 3 + 0]);
    float w1 = __ldg(&W_ih[j * 3 + 1]);
    float w2 = __ldg(&W_ih[j * 3 + 2]);
    float bias = __ldg(&b_ih[j]) + __ldg(&b_hh[j]);

    for (int e = j; e < 16 * 3; e += 256) hrow[e] = src[(size_t)base * 3 + e];
    __syncthreads();

#pragma unroll
    for (int n = 0; n < 16; n++) {
        float acc = bias;
        acc = fmaf(hrow[n * 3 + 0], w0, acc);
        acc = fmaf(hrow[n * 3 + 1], w1, acc);
        acc = fmaf(hrow[n * 3 + 2], w2, acc);
        g_P16a[(size_t)(base + n) * G4 + j] = __float2half(acc);
    }
}

// ---------------- fused LSTM + combine + next-layer proj (+ out) ----------------
// Each CTA processes TWO 32-node tiles (grid 313): prologue (W_hh frags, Wl smem)
// amortized, wave tail eliminated.
// SORT (layer 0 only): per-tile prologue bitonic-sorts the raw nbr rows
// (8 warps x 4 shfl-sorts) -> idx smem + g_nbr_sorted gmem for layers 1,2.
// In-loop: gates = P16in[idx_t] (cp.async-staged) + h@W_hh^T; f16x2 activations,
// fp32 cell state. Epilogue per tile: comb = relu([x|agg]@Wl^T+bl);
// NEXT: P16out = comb@Wihn^T + bn;  LAST: out = comb.Wo + bo.

template <int XP, int XIND, bool SORT, bool NEXT, bool LAST>
__global__ __launch_bounds__(256, 2) void lstm_fused_kernel(
    const float* __restrict__ W_hh,
    const __half* __restrict__ P16in,
    const __half* __restrict__ x16,
    const float*  __restrict__ xf32,
    const int*    __restrict__ nbr_raw,
    const float*  __restrict__ Wl,
    const float*  __restrict__ bl,
    const float*  __restrict__ Wihn,   // next layer W_ih [256,64]
    const float*  __restrict__ bihn,
    const float*  __restrict__ bhhn,
    const float*  __restrict__ Wo,
    const float*  __restrict__ bo,
    __half* __restrict__ P16out,
    __half* __restrict__ h16out,
    float* __restrict__ outp)
{
    extern __shared__ char dsm[];
    constexpr int HB0    = 2 * XSTG;
    constexpr int KD2    = XP + 64;
    constexpr int KDT    = XIND + 64;
    constexpr int WPITCH = KD2 + 8;
    constexpr int WLOFF  = HB0 + 8192;
    constexpr int XPITCH = XP + 8;
    constexpr int XSOFF  = WLOFF + 64 * WPITCH * 2;
    constexpr int IDXOFF = XSOFF + MT * XPITCH * 2;
    constexpr int KKC    = KD2 / 16;
    constexpr int KKXT   = XP / 16;

    const int tid  = threadIdx.x;
    const int w    = tid >> 5;
    const int lane = tid & 31;
    const int grp  = lane >> 2;
    const int tig  = lane & 3;
    const int col0 = 8 * w + tig * 2;

    const uint32_t sm32 = (uint32_t)__cvta_generic_to_shared(dsm);
    int* idx_smp = reinterpret_cast<int*>(dsm + IDXOFF);

    // ================ CTA-invariant prologue ================
    // ---- W_hh -> B fragments (float2 loads) ----
    uint32_t Bhh[4][4][2];
#pragma unroll
    for (int g = 0; g < 4; g++) {
        const float* row = W_hh + (size_t)(64 * g + 8 * w + grp) * HH;
#pragma unroll
        for (int kk = 0; kk < 4; kk++) {
            const float2* rk = reinterpret_cast<const float2*>(row + kk * 16 + tig * 2);
            Bhh[g][kk][0] = pack2f(__ldg(rk));
            Bhh[g][kk][1] = pack2f(__ldg(rk + 4));
        }
    }
    // ---- Wl -> smem fp16 ----
    {
        __half* wsm = reinterpret_cast<__half*>(dsm + WLOFF);
        for (int e = tid; e < 64 * KD2; e += 256) {
            int n = e / KD2, k = e - n * KD2;
            float v;
            if (k < XP) v = (k < XIND) ? __ldg(&Wl[n * KDT + k]) : 0.0f;
            else        v = __ldg(&Wl[n * KDT + XIND + (k - XP)]);
            wsm[n * WPITCH + k] = __float2half(v);
        }
    }
    // ---- ldmatrix addrs for h / store addrs (tile-invariant) ----
    uint32_t lmh[2][4];
    {
        int sub = lane >> 3;
#pragma unroll
        for (int m = 0; m < 2; m++)
#pragma unroll
            for (int kk = 0; kk < 4; kk++) {
                int rr   = m * 16 + (lane & 7) + (sub & 1) * 8;
                int gcol = kk * 2 + (sub >> 1);
                int pc   = (gcol ^ (rr & 7));
                lmh[m][kk] = sm32 + (uint32_t)(HB0 + rr * 128 + pc * 16);
            }
    }
    uint32_t sth[4];
    {
        int pc = ((w ^ grp) << 3) + tig * 2;
#pragma unroll
        for (int j = 0; j < 4; j++) {
            int r = (j >> 1) * 16 + (j & 1) * 8 + grp;
            sth[j] = (uint32_t)(HB0 + r * 128 + pc * 2);
        }
    }

    const int sr = tid >> 3;
    const int sj = tid & 7;

    // ================ per-tile loop ================
#pragma unroll 1
    for (int tt = 0; tt < 2; tt++) {
        const int tile = blockIdx.x * 2 + tt;
        if (tile >= NTILE) break;
        const int base = tile * MT;

        __syncthreads();   // prior tile's epilogue smem reads complete

        // ---- neighbor indices: sort (L0) or load ----
        if constexpr (SORT) {
#pragma unroll
            for (int q = 0; q < 4; q++) {
                int r = w * 4 + q;
                int v = __ldg(&nbr_raw[(base + r) * DD + lane]);
#pragma unroll
                for (int k = 2; k <= 32; k <<= 1) {
#pragma unroll
                    for (int j = k >> 1; j > 0; j >>= 1) {
                        int p = __shfl_xor_sync(0xffffffffu, v, j);
                        bool keepMin = (((lane & j) == 0) == ((lane & k) == 0));
                        int mn = min(v, p), mx = max(v, p);
                        v = keepMin ? mn : mx;
                    }
                }
                idx_smp[r * DD + lane] = v;
                g_nbr_sorted[(base + r) * DD + lane] = v;   // for layers 1,2
            }
        } else {
            for (int e = tid; e < MT * DD; e += 256)
                idx_smp[e] = __ldg(&g_nbr_sorted[base * DD + e]);
        }

        // ---- zero h buffers ----
        for (int e = tid; e < 2 * MT * HH / 2; e += 256)
            reinterpret_cast<uint32_t*>(dsm + HB0)[e] = 0u;

        // ---- combine-x -> smem fp16 ----
        {
            __half* xsm = reinterpret_cast<__half*>(dsm + XSOFF);
            for (int e = tid; e < MT * XP; e += 256) {
                int r = e / XP, k = e - r * XP;
                __half v;
                if (XIND == 3) v = __float2half(k < 3 ? __ldg(&xf32[(base + r) * 3 + k]) : 0.0f);
                else           v = x16[(size_t)(base + r) * HH + k];
                xsm[r * XPITCH + k] = v;
            }
        }
        __syncthreads();   // idx_smp, h buffers, xsm (+ first tile: Wl) visible

        // ---- preload stage(0) ----
        {
            int idx = idx_smp[sr * DD + 0];
#pragma unroll
            for (int g = 0; g < 4; g++)
                cp_async16(sm32 + (uint32_t)((sr * 33 + g * 8 + sj) * 16),
                           P16in + (size_t)idx * G4 + (g * 8 + sj) * 8);
            asm volatile("cp.async.commit_group;");
        }

        float cst[2][4] = {{0.f,0.f,0.f,0.f},{0.f,0.f,0.f,0.f}};

#pragma unroll 1
        for (int t = 0; t < DD; t++) {
            const int sb  = (t & 1) * XSTG;
            const uint32_t hrb = (uint32_t)(((t & 1) ^ 1) * 4096);
            const uint32_t hwb = (uint32_t)((t & 1) * 4096);

            asm volatile("cp.async.wait_group 0;" ::: "memory");
            __syncthreads();

            if (t < DD - 1) {
                int idx = idx_smp[sr * DD + (t + 1)];
                uint32_t sbn = sm32 + (uint32_t)(((t + 1) & 1) * XSTG);
#pragma unroll
                for (int g = 0; g < 4; g++)
                    cp_async16(sbn + (uint32_t)((sr * 33 + g * 8 + sj) * 16),
                               P16in + (size_t)idx * G4 + (g * 8 + sj) * 8);
            }
            asm volatile("cp.async.commit_group;");

            // ---- gate init ----
            float cur[2][4][4];
#pragma unroll
            for (int m = 0; m < 2; m++)
#pragma unroll
                for (int g = 0; g < 4; g++) {
                    int r0 = m * 16 + grp;
                    const __half2 v0 = *reinterpret_cast<const __half2*>(
                        dsm + sb + (r0 * 33 + g * 8 + w) * 16 + tig * 4);
                    const __half2 v1 = *reinterpret_cast<const __half2*>(
                        dsm + sb + ((r0 + 8) * 33 + g * 8 + w) * 16 + tig * 4);
                    float2 f0 = __half22float2(v0);
                    float2 f1 = __half22float2(v1);
                    cur[m][g][0] = f0.x; cur[m][g][1] = f0.y;
                    cur[m][g][2] = f1.x; cur[m][g][3] = f1.y;
                }

            // ---- gates += h(t-1) @ W_hh^T ----
#pragma unroll
            for (int kk = 0; kk < 4; kk++) {
                uint32_t A0[4], A1[4];
                asm volatile("ldmatrix.sync.aligned.m8n8.x4.shared.b16 {%0,%1,%2,%3}, [%4];"
                             : "=r"(A0[0]), "=r"(A0[1]), "=r"(A0[2]), "=r"(A0[3])
                             : "r"(lmh[0][kk] + hrb));
                asm volatile("ldmatrix.sync.aligned.m8n8.x4.shared.b16 {%0,%1,%2,%3}, [%4];"
                             : "=r"(A1[0]), "=r"(A1[1]), "=r"(A1[2]), "=r"(A1[3])
                             : "r"(lmh[1][kk] + hrb));
#pragma unroll
                for (int g = 0; g < 4; g++) {
                    asm volatile(
                        "mma.sync.aligned.m16n8k16.row.col.f32.f16.f16.f32 "
                        "{%0,%1,%2,%3}, {%4,%5,%6,%7}, {%8,%9}, {%0,%1,%2,%3};"
                        : "+f"(cur[0][g][0]), "+f"(cur[0][g][1]),
                          "+f"(cur[0][g][2]), "+f"(cur[0][g][3])
                        : "r"(A0[0]), "r"(A0[1]), "r"(A0[2]), "r"(A0[3]),
                          "r"(Bhh[g][kk][0]), "r"(Bhh[g][kk][1]));
                    asm volatile(
                        "mma.sync.aligned.m16n8k16.row.col.f32.f16.f16.f32 "
                        "{%0,%1,%2,%3}, {%4,%5,%6,%7}, {%8,%9}, {%0,%1,%2,%3};"
                        : "+f"(cur[1][g][0]), "+f"(cur[1][g][1]),
                          "+f"(cur[1][g][2]), "+f"(cur[1][g][3])
                        : "r"(A1[0]), "r"(A1[1]), "r"(A1[2]), "r"(A1[3]),
                          "r"(Bhh[g][kk][0]), "r"(Bhh[g][kk][1]));
                }
            }

            // ---- activations (f16x2) + cell update (fp32 c) ----
            uint32_t hst[2][2];
#pragma unroll
            for (int m = 0; m < 2; m++)
#pragma unroll
                for (int p = 0; p < 2; p++) {
                    __half2 gi = __floats2half2_rn(cur[m][0][2*p], cur[m][0][2*p+1]);
                    __half2 gf = __floats2half2_rn(cur[m][1][2*p], cur[m][1][2*p+1]);
                    __half2 gg = __floats2half2_rn(cur[m][2][2*p], cur[m][2][2*p+1]);
                    __half2 go = __floats2half2_rn(cur[m][3][2*p], cur[m][3][2*p+1]);
                    __half2 si = sig_h2(gi);
                    __half2 sf = sig_h2(gf);
                    __half2 so = sig_h2(go);
                    __half2 tg = tanh_h2(gg);
                    __half2 ig = __hmul2(si, tg);
                    float2 fig = __half22float2(ig);
                    float2 ff  = __half22float2(sf);
                    float c0 = fmaf(ff.x, cst[m][2*p],     fig.x);
                    float c1 = fmaf(ff.y, cst[m][2*p + 1], fig.y);
                    cst[m][2*p]     = c0;
                    cst[m][2*p + 1] = c1;
                    __half2 tc = tanh_h2(__floats2half2_rn(c0, c1));
                    __half2 h2 = __hmul2(so, tc);
                    hst[m][p] = *reinterpret_cast<uint32_t*>(&h2);
                }

#pragma unroll
            for (int m = 0; m < 2; m++)
#pragma unroll
                for (int p = 0; p < 2; p++)
                    *reinterpret_cast<uint32_t*>(dsm + hwb + sth[m * 2 + p]) = hst[m][p];
        }

        __syncthreads();   // final h (= agg, buffer 1) visible

        // ================= combine epilogue (per tile) =================
        const uint32_t aggb = 4096;
        const uint32_t lmw0 = sm32 + (uint32_t)(WLOFF +
                             ((8 * w + (lane & 7)) * WPITCH + ((lane >> 3) & 1) * 8) * 2);

        float acc[2][4];
        {
            float b0 = __ldg(&bl[col0]), b1 = __ldg(&bl[col0 + 1]);
#pragma unroll
            for (int m = 0; m < 2; m++) {
                acc[m][0] = b0; acc[m][1] = b1; acc[m][2] = b0; acc[m][3] = b1;
            }
        }

#pragma unroll
        for (int kk = 0; kk < KKC; kk++) {
            uint32_t A0[4], A1[4];
            if (kk < KKXT) {
                int sub = lane >> 3;
                int rr0 = (lane & 7) + (sub & 1) * 8;
                int gcol = kk * 2 + (sub >> 1);
                uint32_t a0 = sm32 + (uint32_t)(XSOFF + rr0 * (XPITCH * 2) + gcol * 16);
                uint32_t a1 = a0 + (uint32_t)(16 * XPITCH * 2);
                asm volatile("ldmatrix.sync.aligned.m8n8.x4.shared.b16 {%0,%1,%2,%3}, [%4];"
                             : "=r"(A0[0]), "=r"(A0[1]), "=r"(A0[2]), "=r"(A0[3]) : "r"(a0));
                asm volatile("ldmatrix.sync.aligned.m8n8.x4.shared.b16 {%0,%1,%2,%3}, [%4];"
                             : "=r"(A1[0]), "=r"(A1[1]), "=r"(A1[2]), "=r"(A1[3]) : "r"(a1));
            } else {
                asm volatile("ldmatrix.sync.aligned.m8n8.x4.shared.b16 {%0,%1,%2,%3}, [%4];"
                             : "=r"(A0[0]), "=r"(A0[1]), "=r"(A0[2]), "=r"(A0[3])
                             : "r"(lmh[0][kk - KKXT] + aggb));
                asm volatile("ldmatrix.sync.aligned.m8n8.x4.shared.b16 {%0,%1,%2,%3}, [%4];"
                             : "=r"(A1[0]), "=r"(A1[1]), "=r"(A1[2]), "=r"(A1[3])
                             : "r"(lmh[1][kk - KKXT] + aggb));
            }
            uint32_t B0, B1;
            asm volatile("ldmatrix.sync.aligned.m8n8.x2.shared.b16 {%0,%1}, [%2];"
                         : "=r"(B0), "=r"(B1)
                         : "r"(lmw0 + (uint32_t)(kk * 16 * 2)));
            asm volatile(
                "mma.sync.aligned.m16n8k16.row.col.f32.f16.f16.f32 "
                "{%0,%1,%2,%3}, {%4,%5,%6,%7}, {%8,%9}, {%0,%1,%2,%3};"
                : "+f"(acc[0][0]), "+f"(acc[0][1]), "+f"(acc[0][2]), "+f"(acc[0][3])
                : "r"(A0[0]), "r"(A0[1]), "r"(A0[2]), "r"(A0[3]), "r"(B0), "r"(B1));
            asm volatile(
                "mma.sync.aligned.m16n8k16.row.col.f32.f16.f16.f32 "
                "{%0,%1,%2,%3}, {%4,%5,%6,%7}, {%8,%9}, {%0,%1,%2,%3};"
                : "+f"(acc[1][0]), "+f"(acc[1][1]), "+f"(acc[1][2]), "+f"(acc[1][3])
                : "r"(A1[0]), "r"(A1[1]), "r"(A1[2]), "r"(A1[3]), "r"(B0), "r"(B1));
        }

#pragma unroll
        for (int m = 0; m < 2; m++)
#pragma unroll
            for (int e = 0; e < 4; e++)
                acc[m][e] = fmaxf(acc[m][e], 0.0f);

        if constexpr (LAST) {
            float wo0 = __ldg(&Wo[col0]), wo1 = __ldg(&Wo[col0 + 1]);
            float* part = reinterpret_cast<float*>(dsm);
            __syncthreads();   // stage region reads (gate init) long done; reuse
#pragma unroll
            for (int m = 0; m < 2; m++)
#pragma unroll
                for (int rh = 0; rh < 2; rh++) {
                    int r = m * 16 + rh * 8 + grp;
                    part[r * 33 + w * 4 + tig] =
                        acc[m][rh * 2] * wo0 + acc[m][rh * 2 + 1] * wo1;
                }
            __syncthreads();
            if (tid < MT) {
                float s = 0.0f;
#pragma unroll
                for (int j = 0; j < 32; j++) s += part[tid * 33 + j];
                outp[base + tid] = s + __ldg(&bo[0]);
            }
        }

        if constexpr (NEXT) {
            // ---- comb -> h16out + smem buffer 0 ----
#pragma unroll
            for (int m = 0; m < 2; m++)
#pragma unroll
                for (int p = 0; p < 2; p++) {
                    uint32_t v = pack2(acc[m][2 * p], acc[m][2 * p + 1]);
                    *reinterpret_cast<uint32_t*>(dsm + sth[m * 2 + p]) = v;
                    int r = m * 16 + p * 8 + grp;
                    *reinterpret_cast<uint32_t*>(
                        &h16out[(size_t)(base + r) * HH + col0]) = v;
                }

            // ---- W_ih_next -> B fragments (float2 loads) ----
            uint32_t Bih[4][4][2];
#pragma unroll
            for (int g = 0; g < 4; g++) {
                const float* row = Wihn + (size_t)(64 * g + 8 * w + grp) * HH;
#pragma unroll
                for (int kk = 0; kk < 4; kk++) {
                    const float2* rk = reinterpret_cast<const float2*>(row + kk * 16 + tig * 2);
                    Bih[g][kk][0] = pack2f(__ldg(rk));
                    Bih[g][kk][1] = pack2f(__ldg(rk + 4));
                }
            }
            float bn[4][2];
#pragma unroll
            for (int g = 0; g < 4; g++) {
#pragma unroll
                for (int e = 0; e < 2; e++) {
                    int c = 64 * g + col0 + e;
                    bn[g][e] = __ldg(&bihn[c]) + __ldg(&bhhn[c]);
                }
            }
            __syncthreads();   // comb stores visible

            float pc[2][4][4];
#pragma unroll
            for (int m = 0; m < 2; m++)
#pragma unroll
                for (int g = 0; g < 4; g++) {
                    pc[m][g][0] = bn[g][0]; pc[m][g][1] = bn[g][1];
                    pc[m][g][2] = bn[g][0]; pc[m][g][3] = bn[g][1];
                }
#pragma unroll
            for (int kk = 0; kk < 4; kk++) {
                uint32_t A0[4], A1[4];
                asm volatile("ldmatrix.sync.aligned.m8n8.x4.shared.b16 {%0,%1,%2,%3}, [%4];"
                             : "=r"(A0[0]), "=r"(A0[1]), "=r"(A0[2]), "=r"(A0[3])
                             : "r"(lmh[0][kk]));
                asm volatile("ldmatrix.sync.aligned.m8n8.x4.shared.b16 {%0,%1,%2,%3}, [%4];"
                             : "=r"(A1[0]), "=r"(A1[1]), "=r"(A1[2]), "=r"(A1[3])
                             : "r"(lmh[1][kk]));
#pragma unroll
                for (int g = 0; g < 4; g++) {
                    asm volatile(
                        "mma.sync.aligned.m16n8k16.row.col.f32.f16.f16.f32 "
                        "{%0,%1,%2,%3}, {%4,%5,%6,%7}, {%8,%9}, {%0,%1,%2,%3};"
                        : "+f"(pc[0][g][0]), "+f"(pc[0][g][1]),
                          "+f"(pc[0][g][2]), "+f"(pc[0][g][3])
                        : "r"(A0[0]), "r"(A0[1]), "r"(A0[2]), "r"(A0[3]),
                          "r"(Bih[g][kk][0]), "r"(Bih[g][kk][1]));
                    asm volatile(
                        "mma.sync.aligned.m16n8k16.row.col.f32.f16.f16.f32 "
                        "{%0,%1,%2,%3}, {%4,%5,%6,%7}, {%8,%9}, {%0,%1,%2,%3};"
                        : "+f"(pc[1][g][0]), "+f"(pc[1][g][1]),
                          "+f"(pc[1][g][2]), "+f"(pc[1][g][3])
                        : "r"(A1[0]), "r"(A1[1]), "r"(A1[2]), "r"(A1[3]),
                          "r"(Bih[g][kk][0]), "r"(Bih[g][kk][1]));
                }
            }

#pragma unroll
            for (int m = 0; m < 2; m++)
#pragma unroll
                for (int rh = 0; rh < 2; rh++) {
                    int r = m * 16 + rh * 8 + grp;
#pragma unroll
                    for (int g = 0; g < 4; g++) {
                        __half2 h2 = __floats2half2_rn(pc[m][g][rh * 2], pc[m][g][rh * 2 + 1]);
                        *reinterpret_cast<__half2*>(
                            &P16out[(size_t)(base + r) * G4 + 64 * g + col0]) = h2;
                    }
                }
        }
    }
}

// ---------------- launch ----------------
extern "C" void kernel_launch(void* const* d_in, const int* in_sizes, int n_in,
                              void* d_out, int out_size) {
    const float* node_features = (const float*)d_in[0];
    const int*   nbr           = (const int*)d_in[1];
    const float* W_ih[3] = {(const float*)d_in[2],  (const float*)d_in[8],  (const float*)d_in[14]};
    const float* W_hh[3] = {(const float*)d_in[3],  (const float*)d_in[9],  (const float*)d_in[15]};
    const float* b_ih[3] = {(const float*)d_in[4],  (const float*)d_in[10], (const float*)d_in[16]};
    const float* b_hh[3] = {(const float*)d_in[5],  (const float*)d_in[11], (const float*)d_in[17]};
    const float* Wl[3]   = {(const float*)d_in[6],  (const float*)d_in[12], (const float*)d_in[18]};
    const float* bl[3]   = {(const float*)d_in[7],  (const float*)d_in[13], (const float*)d_in[19]};
    const float* W_out   = (const float*)d_in[20];
    const float* b_out   = (const float*)d_in[21];
    float* out = (float*)d_out;

    void *pPa, *pPb, *pH16;
    cudaGetSymbolAddress(&pPa, g_P16a);
    cudaGetSymbolAddress(&pPb, g_P16b);
    cudaGetSymbolAddress(&pH16, g_hf16);
    __half* Pa  = (__half*)pPa;
    __half* Pb  = (__half*)pPb;
    __half* h16 = (__half*)pH16;

    constexpr int SM_L0 = 2*XSTG + 8192 + 64*(16+64+8)*2 + 32*(16+8)*2 + MT*DD*4;  // 59200
    constexpr int SM_L12= 2*XSTG + 8192 + 64*(64+64+8)*2 + 32*(64+8)*2 + MT*DD*4;  // 68416
    cudaFuncSetAttribute((const void*)lstm_fused_kernel<16,3,true,true,false>,
                         cudaFuncAttributeMaxDynamicSharedMemorySize, SM_L0);
    cudaFuncSetAttribute((const void*)lstm_fused_kernel<64,64,false,true,false>,
                         cudaFuncAttributeMaxDynamicSharedMemorySize, SM_L12);
    cudaFuncSetAttribute((const void*)lstm_fused_kernel<64,64,false,false,true>,
                         cudaFuncAttributeMaxDynamicSharedMemorySize, SM_L12);

    proj16_l0_kernel<<<NN / 16, 256>>>(node_features, W_ih[0], b_ih[0], b_hh[0]);

    // layer 0: sorts nbr in-prologue; reads Pa; epilogue writes h16 + Pb
    lstm_fused_kernel<16,3,true,true,false><<<NCTA, 256, SM_L0>>>(
        W_hh[0], Pa, nullptr, node_features, nbr, Wl[0], bl[0],
        W_ih[1], b_ih[1], b_hh[1], nullptr, nullptr, Pb, h16, nullptr);

    // layer 1: reads Pb + h16; epilogue writes h16 + Pa
    lstm_fused_kernel<64,64,false,true,false><<<NCTA, 256, SM_L12>>>(
        W_hh[1], Pb, h16, nullptr, nullptr, Wl[1], bl[1],
        W_ih[2], b_ih[2], b_hh[2], nullptr, nullptr, Pa, h16, nullptr);

    // layer 2: reads Pa + h16; epilogue reduces out
    lstm_fused_kernel<64,64,false,false,true><<<NCTA, 256, SM_L12>>>(
        W_hh[2], Pa, h16, nullptr, nullptr, Wl[2], bl[2],
        nullptr, nullptr, nullptr, W_out, b_out, nullptr, nullptr, out);
}

// round 17
// speedup vs baseline: 1.1741x; 1.1741x over previous
#include <cuda_runtime.h>
#include <cuda_fp16.h>
#include <cstdint>

#define NN    20000
#define DD    32
#define HH    64
#define G4    256   // 4*H
#define MT    32    // nodes per lstm block
#define NBLK_LSTM (NN / MT)   // 625
#define XSTG  17056           // one P-stage buffer

// ---------------- scratch ----------------
__device__ int    g_nbr_sorted[NN * DD];
__device__ __half g_P16a[(size_t)NN * G4];   // double-buffered fp16 projections
__device__ __half g_P16b[(size_t)NN * G4];
__device__ __half g_hf16[(size_t)NN * HH];   // fp16 layer outputs (combine-x)

// ---------------- helpers ----------------
__device__ __forceinline__ uint32_t pack2(float a, float b) {
    __half2 h = __floats2half2_rn(a, b);
    return *reinterpret_cast<uint32_t*>(&h);
}
__device__ __forceinline__ uint32_t pack2f(float2 v) {
    __half2 h = __floats2half2_rn(v.x, v.y);
    return *reinterpret_cast<uint32_t*>(&h);
}
__device__ __forceinline__ __half2 tanh_h2(__half2 x) {
    uint32_t xi = *reinterpret_cast<uint32_t*>(&x);
    uint32_t yi;
    asm("tanh.approx.f16x2 %0, %1;" : "=r"(yi) : "r"(xi));
    return *reinterpret_cast<__half2*>(&yi);
}
__device__ __forceinline__ __half2 sig_h2(__half2 x) {
    const __half2 h = __float2half2_rn(0.5f);
    return __hfma2(tanh_h2(__hmul2(x, h)), h, h);
}
__device__ __forceinline__ void cp_async16(uint32_t dst_smem, const void* src) {
    asm volatile("cp.async.ca.shared.global [%0], [%1], 16;" :: "r"(dst_smem), "l"(src));
}

// ---------------- layer-0 proj: P16a = x3 @ W_ih^T + b ----------------
__global__ __launch_bounds__(256) void proj16_l0_kernel(const float* __restrict__ src,
                                                        const float* __restrict__ W_ih,
                                                        const float* __restrict__ b_ih,
                                                        const float* __restrict__ b_hh) {
    __shared__ float hrow[16 * 3];
    const int j    = threadIdx.x;
    const int base = blockIdx.x * 16;

    float w0 = __ldg(&W_ih[j * 3 + 0]);
    float w1 = __ldg(&W_ih[j * 3 + 1]);
    float w2 = __ldg(&W_ih[j * 3 + 2]);
    float bias = __ldg(&b_ih[j]) + __ldg(&b_hh[j]);

    for (int e = j; e < 16 * 3; e += 256) hrow[e] = src[(size_t)base * 3 + e];
    __syncthreads();

#pragma unroll
    for (int n = 0; n < 16; n++) {
        float acc = bias;
        acc = fmaf(hrow[n * 3 + 0], w0, acc);
        acc = fmaf(hrow[n * 3 + 1], w1, acc);
        acc = fmaf(hrow[n * 3 + 2], w2, acc);
        g_P16a[(size_t)(base + n) * G4 + j] = __float2half(acc);
    }
}

// ---------------- fused LSTM + combine + next-layer proj (+ out) ----------------
// Exactly the R14 structure (grid 625, 1 tile/CTA, 2 CTAs/SM).
// SORT (layer 0): prologue bitonic-sorts this CTA's 32 raw nbr rows
// (warp w sorts rows [4w,4w+4)) -> idx smem (+ gmem for layers 1,2);
// in-loop idx then comes from smem (only for SORT; layers 1,2 keep direct LDG).
// In-loop: gates = P16in[idx_t] (cp.async-staged) + h@W_hh^T (HMMA K=64);
// f16x2 activations, fp32 cell state.
// Epilogue: comb = relu([x|agg]@Wl^T+bl); NEXT: P16out = comb@Wihn^T + bn;
// LAST: out = comb.Wo + bo.

template <int XP, int XIND, bool SORT, bool NEXT, bool LAST>
__global__ __launch_bounds__(256, 2) void lstm_fused_kernel(
    const float* __restrict__ W_hh,
    const __half* __restrict__ P16in,
    const __half* __restrict__ x16,
    const float*  __restrict__ xf32,
    const int*    __restrict__ nbr_raw,   // raw neighbors (SORT only)
    const float*  __restrict__ Wl,
    const float*  __restrict__ bl,
    const float*  __restrict__ Wihn,      // next layer W_ih [256,64]
    const float*  __restrict__ bihn,
    const float*  __restrict__ bhhn,
    const float*  __restrict__ Wo,
    const float*  __restrict__ bo,
    __half* __restrict__ P16out,
    __half* __restrict__ h16out,
    float* __restrict__ outp)
{
    extern __shared__ char dsm[];
    constexpr int HB0    = 2 * XSTG;
    constexpr int KD2    = XP + 64;
    constexpr int KDT    = XIND + 64;
    constexpr int WPITCH = KD2 + 8;
    constexpr int WLOFF  = HB0 + 8192;
    constexpr int XPITCH = XP + 8;
    constexpr int XSOFF  = WLOFF + 64 * WPITCH * 2;
    constexpr int IDXOFF = XSOFF + MT * XPITCH * 2;   // [MT][DD] int (SORT only)
    constexpr int KKC    = KD2 / 16;
    constexpr int KKXT   = XP / 16;

    const int tid  = threadIdx.x;
    const int w    = tid >> 5;
    const int lane = tid & 31;
    const int grp  = lane >> 2;
    const int tig  = lane & 3;
    const int base = blockIdx.x * MT;
    const int col0 = 8 * w + tig * 2;

    const uint32_t sm32 = (uint32_t)__cvta_generic_to_shared(dsm);
    int* idx_smp = reinterpret_cast<int*>(dsm + IDXOFF);

    // ---- W_hh -> B fragments (float2 loads) ----
    uint32_t Bhh[4][4][2];
#pragma unroll
    for (int g = 0; g < 4; g++) {
        const float* row = W_hh + (size_t)(64 * g + 8 * w + grp) * HH;
#pragma unroll
        for (int kk = 0; kk < 4; kk++) {
            const float2* rk = reinterpret_cast<const float2*>(row + kk * 16 + tig * 2);
            Bhh[g][kk][0] = pack2f(__ldg(rk));
            Bhh[g][kk][1] = pack2f(__ldg(rk + 4));
        }
    }

    // ---- SORT (layer 0): warp w bitonic-sorts its own rows [4w, 4w+4) ----
    if constexpr (SORT) {
#pragma unroll
        for (int q = 0; q < 4; q++) {
            int r = w * 4 + q;
            int v = __ldg(&nbr_raw[(base + r) * DD + lane]);
#pragma unroll
            for (int k = 2; k <= 32; k <<= 1) {
#pragma unroll
                for (int j = k >> 1; j > 0; j >>= 1) {
                    int p = __shfl_xor_sync(0xffffffffu, v, j);
                    bool keepMin = (((lane & j) == 0) == ((lane & k) == 0));
                    int mn = min(v, p), mx = max(v, p);
                    v = keepMin ? mn : mx;
                }
            }
            idx_smp[r * DD + lane] = v;
            g_nbr_sorted[(base + r) * DD + lane] = v;   // for layers 1,2
        }
        __syncwarp();   // thread sr in this warp reads rows [4w,4w+4) below
    }

    // ---- Wl -> smem fp16 ----
    {
        __half* wsm = reinterpret_cast<__half*>(dsm + WLOFF);
        for (int e = tid; e < 64 * KD2; e += 256) {
            int n = e / KD2, k = e - n * KD2;
            float v;
            if (k < XP) v = (k < XIND) ? __ldg(&Wl[n * KDT + k]) : 0.0f;
            else        v = __ldg(&Wl[n * KDT + XIND + (k - XP)]);
            wsm[n * WPITCH + k] = __float2half(v);
        }
    }
    // ---- combine-x -> smem fp16 ----
    {
        __half* xsm = reinterpret_cast<__half*>(dsm + XSOFF);
        for (int e = tid; e < MT * XP; e += 256) {
            int r = e / XP, k = e - r * XP;
            __half v;
            if (XIND == 3) v = __float2half(k < 3 ? __ldg(&xf32[(base + r) * 3 + k]) : 0.0f);
            else           v = x16[(size_t)(base + r) * HH + k];
            xsm[r * XPITCH + k] = v;
        }
    }

    // ---- ldmatrix addrs for h ----
    uint32_t lmh[2][4];
    {
        int sub = lane >> 3;
#pragma unroll
        for (int m = 0; m < 2; m++)
#pragma unroll
            for (int kk = 0; kk < 4; kk++) {
                int rr   = m * 16 + (lane & 7) + (sub & 1) * 8;
                int gcol = kk * 2 + (sub >> 1);
                int pc   = (gcol ^ (rr & 7));
                lmh[m][kk] = sm32 + (uint32_t)(HB0 + rr * 128 + pc * 16);
            }
    }
    uint32_t sth[4];
    {
        int pc = ((w ^ grp) << 3) + tig * 2;
#pragma unroll
        for (int j = 0; j < 4; j++) {
            int r = (j >> 1) * 16 + (j & 1) * 8 + grp;
            sth[j] = (uint32_t)(HB0 + r * 128 + pc * 2);
        }
    }

    const int sr = tid >> 3;     // rows [4w, 4w+4) -> same warp as SORT writer
    const int sj = tid & 7;
    const int nbase = (base + sr) * DD;

    for (int e = tid; e < 2 * MT * HH / 2; e += 256)
        reinterpret_cast<uint32_t*>(dsm + HB0)[e] = 0u;

    // ---- preload stage(0) ----
    {
        int idx = SORT ? idx_smp[sr * DD + 0] : __ldg(&g_nbr_sorted[nbase + 0]);
#pragma unroll
        for (int g = 0; g < 4; g++)
            cp_async16(sm32 + (uint32_t)((sr * 33 + g * 8 + sj) * 16),
                       P16in + (size_t)idx * G4 + (g * 8 + sj) * 8);
        asm volatile("cp.async.commit_group;");
    }

    float cst[2][4] = {{0.f,0.f,0.f,0.f},{0.f,0.f,0.f,0.f}};

#pragma unroll 1
    for (int t = 0; t < DD; t++) {
        const int sb  = (t & 1) * XSTG;
        const uint32_t hrb = (uint32_t)(((t & 1) ^ 1) * 4096);
        const uint32_t hwb = (uint32_t)((t & 1) * 4096);

        asm volatile("cp.async.wait_group 0;" ::: "memory");
        __syncthreads();

        if (t < DD - 1) {
            int idx = SORT ? idx_smp[sr * DD + (t + 1)]
                           : __ldg(&g_nbr_sorted[nbase + (t + 1)]);
            uint32_t sbn = sm32 + (uint32_t)(((t + 1) & 1) * XSTG);
#pragma unroll
            for (int g = 0; g < 4; g++)
                cp_async16(sbn + (uint32_t)((sr * 33 + g * 8 + sj) * 16),
                           P16in + (size_t)idx * G4 + (g * 8 + sj) * 8);
        }
        asm volatile("cp.async.commit_group;");

        // ---- gate init ----
        float cur[2][4][4];
#pragma unroll
        for (int m = 0; m < 2; m++)
#pragma unroll
            for (int g = 0; g < 4; g++) {
                int r0 = m * 16 + grp;
                const __half2 v0 = *reinterpret_cast<const __half2*>(
                    dsm + sb + (r0 * 33 + g * 8 + w) * 16 + tig * 4);
                const __half2 v1 = *reinterpret_cast<const __half2*>(
                    dsm + sb + ((r0 + 8) * 33 + g * 8 + w) * 16 + tig * 4);
                float2 f0 = __half22float2(v0);
                float2 f1 = __half22float2(v1);
                cur[m][g][0] = f0.x; cur[m][g][1] = f0.y;
                cur[m][g][2] = f1.x; cur[m][g][3] = f1.y;
            }

        // ---- gates += h(t-1) @ W_hh^T ----
#pragma unroll
        for (int kk = 0; kk < 4; kk++) {
            uint32_t A0[4], A1[4];
            asm volatile("ldmatrix.sync.aligned.m8n8.x4.shared.b16 {%0,%1,%2,%3}, [%4];"
                         : "=r"(A0[0]), "=r"(A0[1]), "=r"(A0[2]), "=r"(A0[3])
                         : "r"(lmh[0][kk] + hrb));
            asm volatile("ldmatrix.sync.aligned.m8n8.x4.shared.b16 {%0,%1,%2,%3}, [%4];"
                         : "=r"(A1[0]), "=r"(A1[1]), "=r"(A1[2]), "=r"(A1[3])
                         : "r"(lmh[1][kk] + hrb));
#pragma unroll
            for (int g = 0; g < 4; g++) {
                asm volatile(
                    "mma.sync.aligned.m16n8k16.row.col.f32.f16.f16.f32 "
                    "{%0,%1,%2,%3}, {%4,%5,%6,%7}, {%8,%9}, {%0,%1,%2,%3};"
                    : "+f"(cur[0][g][0]), "+f"(cur[0][g][1]),
                      "+f"(cur[0][g][2]), "+f"(cur[0][g][3])
                    : "r"(A0[0]), "r"(A0[1]), "r"(A0[2]), "r"(A0[3]),
                      "r"(Bhh[g][kk][0]), "r"(Bhh[g][kk][1]));
                asm volatile(
                    "mma.sync.aligned.m16n8k16.row.col.f32.f16.f16.f32 "
                    "{%0,%1,%2,%3}, {%4,%5,%6,%7}, {%8,%9}, {%0,%1,%2,%3};"
                    : "+f"(cur[1][g][0]), "+f"(cur[1][g][1]),
                      "+f"(cur[1][g][2]), "+f"(cur[1][g][3])
                    : "r"(A1[0]), "r"(A1[1]), "r"(A1[2]), "r"(A1[3]),
                      "r"(Bhh[g][kk][0]), "r"(Bhh[g][kk][1]));
            }
        }

        // ---- activations (f16x2) + cell update (fp32 c) ----
        uint32_t hst[2][2];
#pragma unroll
        for (int m = 0; m < 2; m++)
#pragma unroll
            for (int p = 0; p < 2; p++) {
                __half2 gi = __floats2half2_rn(cur[m][0][2*p], cur[m][0][2*p+1]);
                __half2 gf = __floats2half2_rn(cur[m][1][2*p], cur[m][1][2*p+1]);
                __half2 gg = __floats2half2_rn(cur[m][2][2*p], cur[m][2][2*p+1]);
                __half2 go = __floats2half2_rn(cur[m][3][2*p], cur[m][3][2*p+1]);
                __half2 si = sig_h2(gi);
                __half2 sf = sig_h2(gf);
                __half2 so = sig_h2(go);
                __half2 tg = tanh_h2(gg);
                __half2 ig = __hmul2(si, tg);
                float2 fig = __half22float2(ig);
                float2 ff  = __half22float2(sf);
                float c0 = fmaf(ff.x, cst[m][2*p],     fig.x);
                float c1 = fmaf(ff.y, cst[m][2*p + 1], fig.y);
                cst[m][2*p]     = c0;
                cst[m][2*p + 1] = c1;
                __half2 tc = tanh_h2(__floats2half2_rn(c0, c1));
                __half2 h2 = __hmul2(so, tc);
                hst[m][p] = *reinterpret_cast<uint32_t*>(&h2);
            }

#pragma unroll
        for (int m = 0; m < 2; m++)
#pragma unroll
            for (int p = 0; p < 2; p++)
                *reinterpret_cast<uint32_t*>(dsm + hwb + sth[m * 2 + p]) = hst[m][p];
    }

    __syncthreads();   // final h (= agg, buffer 1) visible; buffer 0 dead

    // ================= combine epilogue =================
    const uint32_t aggb = 4096;
    const uint32_t lmw0 = sm32 + (uint32_t)(WLOFF +
                         ((8 * w + (lane & 7)) * WPITCH + ((lane >> 3) & 1) * 8) * 2);

    float acc[2][4];
    {
        float b0 = __ldg(&bl[col0]), b1 = __ldg(&bl[col0 + 1]);
#pragma unroll
        for (int m = 0; m < 2; m++) {
            acc[m][0] = b0; acc[m][1] = b1; acc[m][2] = b0; acc[m][3] = b1;
        }
    }

#pragma unroll
    for (int kk = 0; kk < KKC; kk++) {
        uint32_t A0[4], A1[4];
        if (kk < KKXT) {
            int sub = lane >> 3;
            int rr0 = (lane & 7) + (sub & 1) * 8;
            int gcol = kk * 2 + (sub >> 1);
            uint32_t a0 = sm32 + (uint32_t)(XSOFF + rr0 * (XPITCH * 2) + gcol * 16);
            uint32_t a1 = a0 + (uint32_t)(16 * XPITCH * 2);
            asm volatile("ldmatrix.sync.aligned.m8n8.x4.shared.b16 {%0,%1,%2,%3}, [%4];"
                         : "=r"(A0[0]), "=r"(A0[1]), "=r"(A0[2]), "=r"(A0[3]) : "r"(a0));
            asm volatile("ldmatrix.sync.aligned.m8n8.x4.shared.b16 {%0,%1,%2,%3}, [%4];"
                         : "=r"(A1[0]), "=r"(A1[1]), "=r"(A1[2]), "=r"(A1[3]) : "r"(a1));
        } else {
            asm volatile("ldmatrix.sync.aligned.m8n8.x4.shared.b16 {%0,%1,%2,%3}, [%4];"
                         : "=r"(A0[0]), "=r"(A0[1]), "=r"(A0[2]), "=r"(A0[3])
                         : "r"(lmh[0][kk - KKXT] + aggb));
            asm volatile("ldmatrix.sync.aligned.m8n8.x4.shared.b16 {%0,%1,%2,%3}, [%4];"
                         : "=r"(A1[0]), "=r"(A1[1]), "=r"(A1[2]), "=r"(A1[3])
                         : "r"(lmh[1][kk - KKXT] + aggb));
        }
        uint32_t B0, B1;
        asm volatile("ldmatrix.sync.aligned.m8n8.x2.shared.b16 {%0,%1}, [%2];"
                     : "=r"(B0), "=r"(B1)
                     : "r"(lmw0 + (uint32_t)(kk * 16 * 2)));
        asm volatile(
            "mma.sync.aligned.m16n8k16.row.col.f32.f16.f16.f32 "
            "{%0,%1,%2,%3}, {%4,%5,%6,%7}, {%8,%9}, {%0,%1,%2,%3};"
            : "+f"(acc[0][0]), "+f"(acc[0][1]), "+f"(acc[0][2]), "+f"(acc[0][3])
            : "r"(A0[0]), "r"(A0[1]), "r"(A0[2]), "r"(A0[3]), "r"(B0), "r"(B1));
        asm volatile(
            "mma.sync.aligned.m16n8k16.row.col.f32.f16.f16.f32 "
            "{%0,%1,%2,%3}, {%4,%5,%6,%7}, {%8,%9}, {%0,%1,%2,%3};"
            : "+f"(acc[1][0]), "+f"(acc[1][1]), "+f"(acc[1][2]), "+f"(acc[1][3])
            : "r"(A1[0]), "r"(A1[1]), "r"(A1[2]), "r"(A1[3]), "r"(B0), "r"(B1));
    }

#pragma unroll
    for (int m = 0; m < 2; m++)
#pragma unroll
        for (int e = 0; e < 4; e++)
            acc[m][e] = fmaxf(acc[m][e], 0.0f);

    if constexpr (LAST) {
        float wo0 = __ldg(&Wo[col0]), wo1 = __ldg(&Wo[col0 + 1]);
        float* part = reinterpret_cast<float*>(dsm);
#pragma unroll
        for (int m = 0; m < 2; m++)
#pragma unroll
            for (int rh = 0; rh < 2; rh++) {
                int r = m * 16 + rh * 8 + grp;
                part[r * 33 + w * 4 + tig] =
                    acc[m][rh * 2] * wo0 + acc[m][rh * 2 + 1] * wo1;
            }
        __syncthreads();
        if (tid < MT) {
            float s = 0.0f;
#pragma unroll
            for (int j = 0; j < 32; j++) s += part[tid * 33 + j];
            outp[base + tid] = s + __ldg(&bo[0]);
        }
    }

    if constexpr (NEXT) {
        // ---- comb -> h16out + smem buffer 0 ----
#pragma unroll
        for (int m = 0; m < 2; m++)
#pragma unroll
            for (int p = 0; p < 2; p++) {
                uint32_t v = pack2(acc[m][2 * p], acc[m][2 * p + 1]);
                *reinterpret_cast<uint32_t*>(dsm + sth[m * 2 + p]) = v;
                int r = m * 16 + p * 8 + grp;
                *reinterpret_cast<uint32_t*>(
                    &h16out[(size_t)(base + r) * HH + col0]) = v;
            }

        // ---- W_ih_next -> B fragments (float2 loads) ----
        uint32_t Bih[4][4][2];
#pragma unroll
        for (int g = 0; g < 4; g++) {
            const float* row = Wihn + (size_t)(64 * g + 8 * w + grp) * HH;
#pragma unroll
            for (int kk = 0; kk < 4; kk++) {
                const float2* rk = reinterpret_cast<const float2*>(row + kk * 16 + tig * 2);
                Bih[g][kk][0] = pack2f(__ldg(rk));
                Bih[g][kk][1] = pack2f(__ldg(rk + 4));
            }
        }
        float bn[4][2];
#pragma unroll
        for (int g = 0; g < 4; g++) {
#pragma unroll
            for (int e = 0; e < 2; e++) {
                int c = 64 * g + col0 + e;
                bn[g][e] = __ldg(&bihn[c]) + __ldg(&bhhn[c]);
            }
        }
        __syncthreads();   // comb stores visible

        float pc[2][4][4];
#pragma unroll
        for (int m = 0; m < 2; m++)
#pragma unroll
            for (int g = 0; g < 4; g++) {
                pc[m][g][0] = bn[g][0]; pc[m][g][1] = bn[g][1];
                pc[m][g][2] = bn[g][0]; pc[m][g][3] = bn[g][1];
            }
#pragma unroll
        for (int kk = 0; kk < 4; kk++) {
            uint32_t A0[4], A1[4];
            asm volatile("ldmatrix.sync.aligned.m8n8.x4.shared.b16 {%0,%1,%2,%3}, [%4];"
                         : "=r"(A0[0]), "=r"(A0[1]), "=r"(A0[2]), "=r"(A0[3])
                         : "r"(lmh[0][kk]));
            asm volatile("ldmatrix.sync.aligned.m8n8.x4.shared.b16 {%0,%1,%2,%3}, [%4];"
                         : "=r"(A1[0]), "=r"(A1[1]), "=r"(A1[2]), "=r"(A1[3])
                         : "r"(lmh[1][kk]));
#pragma unroll
            for (int g = 0; g < 4; g++) {
                asm volatile(
                    "mma.sync.aligned.m16n8k16.row.col.f32.f16.f16.f32 "
                    "{%0,%1,%2,%3}, {%4,%5,%6,%7}, {%8,%9}, {%0,%1,%2,%3};"
                    : "+f"(pc[0][g][0]), "+f"(pc[0][g][1]),
                      "+f"(pc[0][g][2]), "+f"(pc[0][g][3])
                    : "r"(A0[0]), "r"(A0[1]), "r"(A0[2]), "r"(A0[3]),
                      "r"(Bih[g][kk][0]), "r"(Bih[g][kk][1]));
                asm volatile(
                    "mma.sync.aligned.m16n8k16.row.col.f32.f16.f16.f32 "
                    "{%0,%1,%2,%3}, {%4,%5,%6,%7}, {%8,%9}, {%0,%1,%2,%3};"
                    : "+f"(pc[1][g][0]), "+f"(pc[1][g][1]),
                      "+f"(pc[1][g][2]), "+f"(pc[1][g][3])
                    : "r"(A1[0]), "r"(A1[1]), "r"(A1[2]), "r"(A1[3]),
                      "r"(Bih[g][kk][0]), "r"(Bih[g][kk][1]));
            }
        }

#pragma unroll
        for (int m = 0; m < 2; m++)
#pragma unroll
            for (int rh = 0; rh < 2; rh++) {
                int r = m * 16 + rh * 8 + grp;
#pragma unroll
                for (int g = 0; g < 4; g++) {
                    __half2 h2 = __floats2half2_rn(pc[m][g][rh * 2], pc[m][g][rh * 2 + 1]);
                    *reinterpret_cast<__half2*>(
                        &P16out[(size_t)(base + r) * G4 + 64 * g + col0]) = h2;
                }
            }
    }
}

// ---------------- launch ----------------
extern "C" void kernel_launch(void* const* d_in, const int* in_sizes, int n_in,
                              void* d_out, int out_size) {
    const float* node_features = (const float*)d_in[0];
    const int*   nbr           = (const int*)d_in[1];
    const float* W_ih[3] = {(const float*)d_in[2],  (const float*)d_in[8],  (const float*)d_in[14]};
    const float* W_hh[3] = {(const float*)d_in[3],  (const float*)d_in[9],  (const float*)d_in[15]};
    const float* b_ih[3] = {(const float*)d_in[4],  (const float*)d_in[10], (const float*)d_in[16]};
    const float* b_hh[3] = {(const float*)d_in[5],  (const float*)d_in[11], (const float*)d_in[17]};
    const float* Wl[3]   = {(const float*)d_in[6],  (const float*)d_in[12], (const float*)d_in[18]};
    const float* bl[3]   = {(const float*)d_in[7],  (const float*)d_in[13], (const float*)d_in[19]};
    const float* W_out   = (const float*)d_in[20];
    const float* b_out   = (const float*)d_in[21];
    float* out = (float*)d_out;

    void *pPa, *pPb, *pH16;
    cudaGetSymbolAddress(&pPa, g_P16a);
    cudaGetSymbolAddress(&pPb, g_P16b);
    cudaGetSymbolAddress(&pH16, g_hf16);
    __half* Pa  = (__half*)pPa;
    __half* Pb  = (__half*)pPb;
    __half* h16 = (__half*)pH16;

    // L0 adds MT*DD*4 = 4KB idx region; layers 1,2 keep R14's exact sizes
    constexpr int SM_L0 = 2*XSTG + 8192 + 64*(16+64+8)*2 + 32*(16+8)*2 + MT*DD*4;  // 59200
    constexpr int SM_L12= 2*XSTG + 8192 + 64*(64+64+8)*2 + 32*(64+8)*2;            // 64320
    cudaFuncSetAttribute((const void*)lstm_fused_kernel<16,3,true,true,false>,
                         cudaFuncAttributeMaxDynamicSharedMemorySize, SM_L0);
    cudaFuncSetAttribute((const void*)lstm_fused_kernel<64,64,false,true,false>,
                         cudaFuncAttributeMaxDynamicSharedMemorySize, SM_L12);
    cudaFuncSetAttribute((const void*)lstm_fused_kernel<64,64,false,false,true>,
                         cudaFuncAttributeMaxDynamicSharedMemorySize, SM_L12);

    proj16_l0_kernel<<<NN / 16, 256>>>(node_features, W_ih[0], b_ih[0], b_hh[0]);

    // layer 0: sorts nbr in-prologue; reads Pa; epilogue writes h16 + Pb
    lstm_fused_kernel<16,3,true,true,false><<<NBLK_LSTM, 256, SM_L0>>>(
        W_hh[0], Pa, nullptr, node_features, nbr, Wl[0], bl[0],
        W_ih[1], b_ih[1], b_hh[1], nullptr, nullptr, Pb, h16, nullptr);

    // layer 1: reads Pb + h16; epilogue writes h16 + Pa
    lstm_fused_kernel<64,64,false,true,false><<<NBLK_LSTM, 256, SM_L12>>>(
        W_hh[1], Pb, h16, nullptr, nullptr, Wl[1], bl[1],
        W_ih[2], b_ih[2], b_hh[2], nullptr, nullptr, Pa, h16, nullptr);

    // layer 2: reads Pa + h16; epilogue reduces out
    lstm_fused_kernel<64,64,false,false,true><<<NBLK_LSTM, 256, SM_L12>>>(
        W_hh[2], Pa, h16, nullptr, nullptr, Wl[2], bl[2],
        nullptr, nullptr, nullptr, W_out, b_out, nullptr, nullptr, out);
}